// round 16
// baseline (speedup 1.0000x reference)
#include <cuda_runtime.h>
#include <cuda_fp16.h>
#include <cstdint>

// Problem constants
#define BB 2
#define TT 2048
#define CC 1024
#define NH 16
#define NKV 8
#define HD 64
#define BT (BB*TT)          // 4096

// ---------------- scratch (device globals) ----------------------------------
__device__ float g_qkvbuf[BT * 2048];          // fused [q(1024)|k(512)|v(512)]

__device__ __half g_xh[BT * CC];               // x fp16
__device__ __half g_wch[CC * 2048];            // Wq|Wk|Wv fp16 [K,2048]
__device__ __half g_wph[CC * CC];              // Wproj fp16 [K,N]

__device__ __half g_qattn[BB*NH*TT*HD];        // [b,h,t,d] fp16 (pre-scaled log2e/8)
__device__ __half g_kattn[BB*NKV*TT*HD];       // [b,kh,t,d]
__device__ __half g_vattn[BB*NKV*TT*HD];
__device__ __half g_yattn[BT * CC];            // attn out fp16 [bt, h*d]

// ---------------- PTX helpers ------------------------------------------------
#define LDSM4(r0,r1,r2,r3,addr) \
    asm volatile("ldmatrix.sync.aligned.m8n8.x4.shared.b16 {%0,%1,%2,%3}, [%4];" \
                 : "=r"(r0),"=r"(r1),"=r"(r2),"=r"(r3) : "r"(addr))
#define LDSM4T(r0,r1,r2,r3,addr) \
    asm volatile("ldmatrix.sync.aligned.m8n8.x4.trans.shared.b16 {%0,%1,%2,%3}, [%4];" \
                 : "=r"(r0),"=r"(r1),"=r"(r2),"=r"(r3) : "r"(addr))
#define MMA16816H(d, a, b0, b1) \
    asm volatile("mma.sync.aligned.m16n8k16.row.col.f32.f16.f16.f32 " \
                 "{%0,%1,%2,%3}, {%4,%5,%6,%7}, {%8,%9}, {%0,%1,%2,%3};" \
                 : "+f"(d[0]),"+f"(d[1]),"+f"(d[2]),"+f"(d[3]) \
                 : "r"(a[0]),"r"(a[1]),"r"(a[2]),"r"(a[3]), "r"(b0),"r"(b1))
#define CP16(dst, src) \
    asm volatile("cp.async.cg.shared.global [%0], [%1], 16;" :: "r"(dst), "l"(src))
#define CP_COMMIT asm volatile("cp.async.commit_group;")
#define CP_WAIT(N) asm volatile("cp.async.wait_group %0;" :: "n"(N))
#define CVTF16X2(r, lo, hi) \
    asm("cvt.rn.f16x2.f32 %0, %1, %2;" : "=r"(r) : "f"(hi), "f"(lo))
#define HEX2(r, a) \
    asm("ex2.approx.f16x2 %0, %1;" : "=r"(r) : "r"(a))

__device__ __forceinline__ uint2 cvt4h(float4 v) {
    uint32_t a, b;
    CVTF16X2(a, v.x, v.y);
    CVTF16X2(b, v.z, v.w);
    return make_uint2(a, b);
}

#define QSCALE (0.125f * 1.4426950408889634f)
#define RMS_EPS 1.1920929e-07f

// ---------------- fused conversion: all fp32 inputs -> fp16 ------------------
__global__ __launch_bounds__(256)
void convert_all(const float* __restrict__ x,  const float* __restrict__ Wq,
                 const float* __restrict__ Wk, const float* __restrict__ Wv,
                 const float* __restrict__ Wp)
{
    const int i4 = blockIdx.x * 256 + threadIdx.x;
    if (i4 < 1048576) {
        *(uint2*)(g_xh + (size_t)i4 * 4) = cvt4h(*(const float4*)(x + (size_t)i4 * 4));
    } else if (i4 < 1310720) {
        int j = (i4 - 1048576) * 4;
        int r = j >> 10, c = j & 1023;
        *(uint2*)(g_wch + (size_t)r * 2048 + c) = cvt4h(*(const float4*)(Wq + j));
    } else if (i4 < 1441792) {
        int j = (i4 - 1310720) * 4;
        int r = j >> 9, c = j & 511;
        *(uint2*)(g_wch + (size_t)r * 2048 + 1024 + c) = cvt4h(*(const float4*)(Wk + j));
    } else if (i4 < 1572864) {
        int j = (i4 - 1441792) * 4;
        int r = j >> 9, c = j & 511;
        *(uint2*)(g_wch + (size_t)r * 2048 + 1536 + c) = cvt4h(*(const float4*)(Wv + j));
    } else {
        int j = (i4 - 1572864) * 4;
        *(uint2*)(g_wph + j) = cvt4h(*(const float4*)(Wp + j));
    }
}

// ---------------- GEMM: C = A @ B, fp16 single, fp32 out ---------------------
// BM=128, BN=64, BK=32.  256 thr, 8 warps (4m x 2n), warp tile 32x32.
// 3-stage cp.async.  Small tiles -> 3 CTAs/SM -> better wave balance.
#define GSTAGE 14848
// stage: A@0 (128x40x2=10240), B@10240 (32x72x2=4608)

__global__ __launch_bounds__(256)
void gemm_f16(const __half* __restrict__ Ag, const __half* __restrict__ Bg,
              float* __restrict__ C, int M, int N, int K)
{
    extern __shared__ char sm[];
    const int tid = threadIdx.x;
    const int lane = tid & 31, wid = tid >> 5;
    const int warp_m = wid >> 1, warp_n = wid & 1;     // 4 x 2
    const int gid = lane >> 2, tig = lane & 3;
    const int lane15 = lane & 15, lhi8 = (lane >> 4) * 8;
    const int m0 = blockIdx.y * 128, n0 = blockIdx.x * 64;
    const uint32_t sb = (uint32_t)__cvta_generic_to_shared(sm);

    const int cc0 = tid * 2;
    const int ar = cc0 >> 2, ac = cc0 & 3;    // A: row, 16B chunk pair
    const int br = tid >> 3, bc8 = tid & 7;   // B: row 0..31, 16B chunk 0..7

    float acc[2][4][4];
#pragma unroll
    for (int i = 0; i < 2; i++)
#pragma unroll
        for (int j = 0; j < 4; j++)
#pragma unroll
            for (int r = 0; r < 4; r++) acc[i][j][r] = 0.f;

#define GEMM_LOAD(stg, k0) do { \
    uint32_t s_ = sb + (stg) * GSTAGE; \
    const __half* p_; \
    p_ = Ag + (size_t)(m0 + ar) * K + (k0) + ac * 8; \
    CP16(s_ + ar*80 + ac*16, p_); CP16(s_ + ar*80 + ac*16 + 16, p_ + 8); \
    p_ = Bg + (size_t)((k0) + br) * N + n0 + bc8 * 8; \
    CP16(s_ + 10240 + br*144 + bc8*16, p_); \
    CP_COMMIT; \
} while (0)

    const int ktiles = K >> 5;
    GEMM_LOAD(0, 0);
    GEMM_LOAD(1, 32);

    int stg = 0;
    for (int t = 0; t < ktiles; t++) {
        if (t + 1 < ktiles) CP_WAIT(1); else CP_WAIT(0);
        __syncthreads();
        if (t + 2 < ktiles) {
            int ns = stg + 2; if (ns >= 3) ns -= 3;
            GEMM_LOAD(ns, (t + 2) * 32);
        }

        const uint32_t sA = sb + stg * GSTAGE;
        const uint32_t sB = sA + 10240;

#pragma unroll
        for (int ks = 0; ks < 2; ks++) {
            const uint32_t a_off = (uint32_t)((warp_m * 32 + lane15) * 80 + (ks * 16 + lhi8) * 2);
            const uint32_t b_off = (uint32_t)((ks * 16 + lane15) * 144 + (warp_n * 32 + lhi8) * 2);

            uint32_t a[2][4];
            uint32_t bh[2][4];
#pragma unroll
            for (int mf = 0; mf < 2; mf++)
                LDSM4(a[mf][0],a[mf][1],a[mf][2],a[mf][3], sA + a_off + (uint32_t)(mf * 16 * 80));
#pragma unroll
            for (int p = 0; p < 2; p++)
                LDSM4T(bh[p][0],bh[p][1],bh[p][2],bh[p][3], sB + b_off + (uint32_t)(p * 32));
#pragma unroll
            for (int mf = 0; mf < 2; mf++)
#pragma unroll
                for (int nf = 0; nf < 4; nf++) {
                    const int p = nf >> 1, q = (nf & 1) * 2;
                    MMA16816H(acc[mf][nf], a[mf], bh[p][q], bh[p][q+1]);
                }
        }
        stg++; if (stg == 3) stg = 0;
    }

#pragma unroll
    for (int mf = 0; mf < 2; mf++) {
#pragma unroll
        for (int nf = 0; nf < 4; nf++) {
            const int row = m0 + warp_m * 32 + mf * 16 + gid;
            const int col = n0 + warp_n * 32 + nf * 8 + tig * 2;
            *(float2*)&C[(size_t)row * N + col] = make_float2(acc[mf][nf][0], acc[mf][nf][1]);
            *(float2*)&C[(size_t)(row + 8) * N + col] = make_float2(acc[mf][nf][2], acc[mf][nf][3]);
        }
    }
}

// ---------------- postprocess: gate+ve, RoPE, rmsnorm, fp16 out --------------
// q pre-scaled by log2e/8 so attention scores are already in the exp2 domain.
__global__ __launch_bounds__(256)
void postproc(const float* __restrict__ x, const float* __restrict__ ve,
              const float* __restrict__ cosb, const float* __restrict__ sinb,
              const float* __restrict__ Wgate)
{
    const int bt = blockIdx.x;
    const int b = bt >> 11, t = bt & (TT - 1);
    const int tid = threadIdx.x;
    const float* qkv = g_qkvbuf + (size_t)bt * 2048;

    __shared__ float gate[NKV];
    if (tid < NKV) {
        float acc = 0.f;
        const float* xr = x + (size_t)bt * CC;
#pragma unroll
        for (int c = 0; c < 32; c++) acc += xr[c] * Wgate[c * NKV + tid];
        gate[tid] = 2.f / (1.f + expf(-acc));
    }
    __syncthreads();

    for (int i = tid; i < NKV * HD; i += 256) {
        int hh = i >> 6, d = i & 63;
        float vv = qkv[1536 + i] + gate[hh] * ve[(size_t)bt * 512 + i];
        g_vattn[(((size_t)b * NKV + hh) * TT + t) * HD + d] = __float2half(vv);
    }

    const int w = tid >> 5, lane = tid & 31;
    const float cs = cosb[t * 32 + lane];
    const float sn = sinb[t * 32 + lane];

#pragma unroll
    for (int qi = 0; qi < 2; qi++) {
        int h = 2 * w + qi;
        const float* qr = qkv + h * HD;
        float x1 = qr[lane], x2 = qr[lane + 32];
        float r1 = x1 * cs + x2 * sn;
        float r2 = -x1 * sn + x2 * cs;
        float ss = r1 * r1 + r2 * r2;
#pragma unroll
        for (int o = 16; o; o >>= 1) ss += __shfl_xor_sync(0xffffffffu, ss, o);
        float sc = rsqrtf(ss * (1.f / 64.f) + RMS_EPS) * QSCALE;
        size_t idx = (((size_t)b * NH + h) * TT + t) * HD;
        g_qattn[idx + lane]      = __float2half(r1 * sc);
        g_qattn[idx + lane + 32] = __float2half(r2 * sc);
    }
    {
        const float* kr = qkv + 1024 + w * HD;
        float x1 = kr[lane], x2 = kr[lane + 32];
        float r1 = x1 * cs + x2 * sn;
        float r2 = -x1 * sn + x2 * cs;
        float ss = r1 * r1 + r2 * r2;
#pragma unroll
        for (int o = 16; o; o >>= 1) ss += __shfl_xor_sync(0xffffffffu, ss, o);
        float sc = rsqrtf(ss * (1.f / 64.f) + RMS_EPS);
        size_t idx = (((size_t)b * NKV + w) * TT + t) * HD;
        g_kattn[idx + lane]      = __float2half(r1 * sc);
        g_kattn[idx + lane + 32] = __float2half(r2 * sc);
    }
}

// ---------------- tensor-core flash attention (fp16, exp2, l-via-MMA) --------
// BM=64, BN=64, 4 warps. smem: Q@0 (9216), 2 stages {K,V} at 9216+stg*18432,
// ones block @46080.  Total 46592.  (R11 configuration — best measured.)
__global__ __launch_bounds__(128)
void attn_mma(const int* __restrict__ wptr)
{
    extern __shared__ char sm[];
    const uint32_t sb = (uint32_t)__cvta_generic_to_shared(sm);
    const uint32_t sQ = sb;
    const uint32_t sOnes = sb + 46080;

    const int qt0 = (int)(gridDim.x - 1 - blockIdx.x) * 64;   // heavy blocks first
    const int bh = blockIdx.y;
    const int b = bh >> 4, h = bh & 15;
    const int window = *wptr;
    const bool is_local = (h >= 8);
    const int kvh = is_local ? 4 + ((h - 8) >> 1) : (h >> 1);

    const __half* qb = g_qattn + ((size_t)(b * NH + h) * TT) * HD;
    const __half* kb = g_kattn + ((size_t)(b * NKV + kvh) * TT) * HD;
    const __half* vb = g_vattn + ((size_t)(b * NKV + kvh) * TT) * HD;

    const int tid = threadIdx.x;
    const int lane = tid & 31, wid = tid >> 5;
    const int gid = lane >> 2, tig = lane & 3;
    const int lane15 = lane & 15, lhi8 = (lane >> 4) * 8;
    const int krow = (lane & 7) | ((lane & 16) >> 1);
    const int kc8 = lane & 8;

#define ATT_LOAD(stg, ktv) do { \
    uint32_t base_ = sb + 9216 + (stg) * 18432; \
    for (int c = tid; c < 512; c += 128) { \
        int row_ = c >> 3, c8_ = c & 7; \
        size_t g_ = (size_t)((ktv) + row_) * HD + c8_ * 8; \
        uint32_t d_ = base_ + row_ * 144 + c8_ * 16; \
        CP16(d_, kb + g_); CP16(d_ + 9216, vb + g_); \
    } CP_COMMIT; \
} while (0)

    int t0 = 0;
    if (is_local) { int s = qt0 - window; t0 = (s > 0 ? s : 0) & ~63; }
    const int nt = (qt0 - t0) / 64 + 1;

    if (tid < 128) {
        int k = tid >> 3, c2 = (tid & 7) * 2;
        uint32_t v = (c2 == 0) ? 0x00003C00u : 0u;
        asm volatile("st.shared.b32 [%0], %1;" :: "r"(sOnes + k * 32 + c2 * 2), "r"(v));
    }

    for (int c = tid; c < 512; c += 128) {
        int row = c >> 3, c8 = c & 7;
        CP16(sQ + row * 144 + c8 * 16, qb + (size_t)(qt0 + row) * HD + c8 * 8);
    }
    CP_COMMIT;
    ATT_LOAD(0, t0);
    CP_WAIT(1);
    __syncthreads();

    uint32_t qf[4][4];
    {
        const uint32_t qa = (uint32_t)((wid * 16 + lane15) * 144 + lhi8 * 2);
#pragma unroll
        for (int ks = 0; ks < 4; ks++)
            LDSM4(qf[ks][0],qf[ks][1],qf[ks][2],qf[ks][3], sQ + qa + ks * 32);
    }
    uint32_t ob0, ob1, ob2, ob3;
    LDSM4T(ob0, ob1, ob2, ob3, sOnes + (uint32_t)(lane15 * 32 + lhi8 * 2));
    (void)ob2; (void)ob3;

    float o[8][4];
#pragma unroll
    for (int nf = 0; nf < 8; nf++)
#pragma unroll
        for (int r = 0; r < 4; r++) o[nf][r] = 0.f;
    float ol[4] = {0.f, 0.f, 0.f, 0.f};
    float m0r = -1e30f, m1r = -1e30f;

    const int i0 = qt0 + wid * 16 + gid, i1 = i0 + 8;

    for (int it = 0; it < nt; it++) {
        const int kt = t0 + it * 64;
        const int stg = it & 1;
        if (it + 1 < nt) { ATT_LOAD(stg ^ 1, kt + 64); CP_WAIT(1); }
        else             { CP_WAIT(0); }
        __syncthreads();

        const uint32_t sK = sb + 9216 + stg * 18432;
        const uint32_t sV = sK + 9216;

        float s[8][4];
#pragma unroll
        for (int nf = 0; nf < 8; nf++)
#pragma unroll
            for (int r = 0; r < 4; r++) s[nf][r] = 0.f;
#pragma unroll
        for (int ks = 0; ks < 4; ks++) {
#pragma unroll
            for (int g = 0; g < 4; g++) {
                const uint32_t ka = (uint32_t)((g * 16 + krow) * 144 + (ks * 16 + kc8) * 2);
                uint32_t b0,b1,b2,b3;
                LDSM4(b0,b1,b2,b3, sK + ka);
                MMA16816H(s[2*g],   qf[ks], b0, b1);
                MMA16816H(s[2*g+1], qf[ks], b2, b3);
            }
        }

        const bool need_mask = (kt + 64 > qt0) ||
                               (is_local && kt + window < qt0 + 64);
        if (need_mask) {
#pragma unroll
            for (int nf = 0; nf < 8; nf++) {
                int j0 = kt + nf * 8 + tig * 2, j1 = j0 + 1;
                bool k00 = (j0 <= i0) && (!is_local || j0 >= i0 - window);
                bool k01 = (j1 <= i0) && (!is_local || j1 >= i0 - window);
                bool k10 = (j0 <= i1) && (!is_local || j0 >= i1 - window);
                bool k11 = (j1 <= i1) && (!is_local || j1 >= i1 - window);
                if (!k00) s[nf][0] = -1e30f;
                if (!k01) s[nf][1] = -1e30f;
                if (!k10) s[nf][2] = -1e30f;
                if (!k11) s[nf][3] = -1e30f;
            }
        }

        float t0m = -1e30f, t1m = -1e30f;
#pragma unroll
        for (int nf = 0; nf < 8; nf++) {
            t0m = fmaxf(t0m, fmaxf(s[nf][0], s[nf][1]));
            t1m = fmaxf(t1m, fmaxf(s[nf][2], s[nf][3]));
        }
        t0m = fmaxf(t0m, __shfl_xor_sync(0xffffffffu, t0m, 1));
        t0m = fmaxf(t0m, __shfl_xor_sync(0xffffffffu, t0m, 2));
        t1m = fmaxf(t1m, __shfl_xor_sync(0xffffffffu, t1m, 1));
        t1m = fmaxf(t1m, __shfl_xor_sync(0xffffffffu, t1m, 2));
        float mn0 = fmaxf(m0r, t0m), mn1 = fmaxf(m1r, t1m);
        float cr0 = exp2f(m0r - mn0), cr1 = exp2f(m1r - mn1);
        m0r = mn0; m1r = mn1;

        bool upd = (cr0 != 1.f) || (cr1 != 1.f);
        if (__any_sync(0xffffffffu, upd)) {
#pragma unroll
            for (int nf = 0; nf < 8; nf++) {
                o[nf][0] *= cr0; o[nf][1] *= cr0; o[nf][2] *= cr1; o[nf][3] *= cr1;
            }
            ol[0] *= cr0; ol[1] *= cr0; ol[2] *= cr1; ol[3] *= cr1;
        }

        uint32_t pp0[8], pp1[8];
#pragma unroll
        for (int nf = 0; nf < 8; nf++) {
            uint32_t d0, d1;
            CVTF16X2(d0, s[nf][0] - mn0, s[nf][1] - mn0);
            CVTF16X2(d1, s[nf][2] - mn1, s[nf][3] - mn1);
            HEX2(pp0[nf], d0);
            HEX2(pp1[nf], d1);
        }

#pragma unroll
        for (int ks = 0; ks < 4; ks++) {
            uint32_t pf[4] = { pp0[2*ks], pp1[2*ks], pp0[2*ks+1], pp1[2*ks+1] };
#pragma unroll
            for (int g = 0; g < 4; g++) {
                const uint32_t va = (uint32_t)((ks * 16 + lane15) * 144 + (g * 16 + lhi8) * 2);
                uint32_t v0,v1,v2,v3;
                LDSM4T(v0,v1,v2,v3, sV + va);
                MMA16816H(o[2*g],   pf, v0, v1);
                MMA16816H(o[2*g+1], pf, v2, v3);
            }
            MMA16816H(ol, pf, ob0, ob1);
        }
        __syncthreads();
    }

    const float l0 = __shfl_sync(0xffffffffu, ol[0], lane & ~3);
    const float l1 = __shfl_sync(0xffffffffu, ol[2], lane & ~3);
    const float inv0 = 1.f / l0, inv1 = 1.f / l1;
    const int row0 = qt0 + wid * 16 + gid;
#pragma unroll
    for (int nf = 0; nf < 8; nf++) {
        const int col = h * 64 + nf * 8 + tig * 2;
        uint32_t u0, u1;
        CVTF16X2(u0, o[nf][0] * inv0, o[nf][1] * inv0);
        CVTF16X2(u1, o[nf][2] * inv1, o[nf][3] * inv1);
        *(uint32_t*)(g_yattn + (size_t)(b * TT + row0) * CC + col) = u0;
        *(uint32_t*)(g_yattn + (size_t)(b * TT + row0 + 8) * CC + col) = u1;
    }
}

// ---------------- launch ------------------------------------------------------
extern "C" void kernel_launch(void* const* d_in, const int* in_sizes, int n_in,
                              void* d_out, int out_size)
{
    const float* x     = (const float*)d_in[0];
    const float* ve    = (const float*)d_in[1];
    const float* cosb  = (const float*)d_in[2];
    const float* sinb  = (const float*)d_in[3];
    const float* Wq    = (const float*)d_in[4];
    const float* Wk    = (const float*)d_in[5];
    const float* Wv    = (const float*)d_in[6];
    const float* Wproj = (const float*)d_in[7];
    const float* Wgate = (const float*)d_in[8];
    const int*   wptr  = (const int*)d_in[9];

    float* qkvbuf;
    cudaGetSymbolAddress((void**)&qkvbuf, g_qkvbuf);
    __half *xh, *wch, *wph, *yh;
    cudaGetSymbolAddress((void**)&xh, g_xh);
    cudaGetSymbolAddress((void**)&wch, g_wch);
    cudaGetSymbolAddress((void**)&wph, g_wph);
    cudaGetSymbolAddress((void**)&yh, g_yattn);

    cudaFuncSetAttribute(gemm_f16, cudaFuncAttributeMaxDynamicSharedMemorySize, 3 * GSTAGE);
    cudaFuncSetAttribute(attn_mma, cudaFuncAttributeMaxDynamicSharedMemorySize, 46592);

    // fused conversion (x, Wq, Wk, Wv, Wproj -> fp16)
    convert_all<<<7168, 256>>>(x, Wq, Wk, Wv, Wproj);

    // fused QKV projection (fp16) -> fp32 qkv    grid: N/64 x M/128
    gemm_f16<<<dim3(32, 32), 256, 3 * GSTAGE>>>(xh, wch, qkvbuf, BT, 2048, CC);

    // gate + ve, rope, rmsnorm -> fp16 q/k/v (q pre-scaled, exp2 domain)
    postproc<<<BT, 256>>>(x, ve, cosb, sinb, Wgate);

    // attention (fp16) -> fp16 y
    attn_mma<<<dim3(TT / 64, BB * NH), 128, 46592>>>(wptr);

    // output projection (fp16) -> d_out
    gemm_f16<<<dim3(16, 32), 256, 3 * GSTAGE>>>(yh, wph, (float*)d_out, BT, 1024, CC);
}

// round 17
// speedup vs baseline: 1.0404x; 1.0404x over previous
#include <cuda_runtime.h>
#include <cuda_fp16.h>
#include <cstdint>

// Problem constants
#define BB 2
#define TT 2048
#define CC 1024
#define NH 16
#define NKV 8
#define HD 64
#define BT (BB*TT)          // 4096

// ---------------- scratch (device globals) ----------------------------------
__device__ float g_qkvbuf[BT * 2048];          // fused [q(1024)|k(512)|v(512)]

__device__ __half g_xh[BT * CC];               // x fp16
__device__ __half g_wch[CC * 2048];            // Wq|Wk|Wv fp16 [K,2048]
__device__ __half g_wph[CC * CC];              // Wproj fp16 [K,N]

__device__ __half g_qattn[BB*NH*TT*HD];        // [b,h,t,d] fp16 (pre-scaled log2e/8)
__device__ __half g_kattn[BB*NKV*TT*HD];       // [b,kh,t,d]
__device__ __half g_vattn[BB*NKV*TT*HD];
__device__ __half g_yattn[BT * CC];            // attn out fp16 [bt, h*d]

// ---------------- PTX helpers ------------------------------------------------
#define LDSM4(r0,r1,r2,r3,addr) \
    asm volatile("ldmatrix.sync.aligned.m8n8.x4.shared.b16 {%0,%1,%2,%3}, [%4];" \
                 : "=r"(r0),"=r"(r1),"=r"(r2),"=r"(r3) : "r"(addr))
#define LDSM4T(r0,r1,r2,r3,addr) \
    asm volatile("ldmatrix.sync.aligned.m8n8.x4.trans.shared.b16 {%0,%1,%2,%3}, [%4];" \
                 : "=r"(r0),"=r"(r1),"=r"(r2),"=r"(r3) : "r"(addr))
#define MMA16816H(d, a, b0, b1) \
    asm volatile("mma.sync.aligned.m16n8k16.row.col.f32.f16.f16.f32 " \
                 "{%0,%1,%2,%3}, {%4,%5,%6,%7}, {%8,%9}, {%0,%1,%2,%3};" \
                 : "+f"(d[0]),"+f"(d[1]),"+f"(d[2]),"+f"(d[3]) \
                 : "r"(a[0]),"r"(a[1]),"r"(a[2]),"r"(a[3]), "r"(b0),"r"(b1))
#define CP16(dst, src) \
    asm volatile("cp.async.cg.shared.global [%0], [%1], 16;" :: "r"(dst), "l"(src))
#define CP_COMMIT asm volatile("cp.async.commit_group;")
#define CP_WAIT(N) asm volatile("cp.async.wait_group %0;" :: "n"(N))
#define CVTF16X2(r, lo, hi) \
    asm("cvt.rn.f16x2.f32 %0, %1, %2;" : "=r"(r) : "f"(hi), "f"(lo))
#define HEX2(r, a) \
    asm("ex2.approx.f16x2 %0, %1;" : "=r"(r) : "r"(a))

__device__ __forceinline__ uint2 cvt4h(float4 v) {
    uint32_t a, b;
    CVTF16X2(a, v.x, v.y);
    CVTF16X2(b, v.z, v.w);
    return make_uint2(a, b);
}

#define QSCALE (0.125f * 1.4426950408889634f)
#define RMS_EPS 1.1920929e-07f
#define SOFTMAX_M 8.0f          // fixed softmax shift (exp2 domain); |s| <= 11.54

// ---------------- fused conversion: all fp32 inputs -> fp16 ------------------
__global__ __launch_bounds__(256)
void convert_all(const float* __restrict__ x,  const float* __restrict__ Wq,
                 const float* __restrict__ Wk, const float* __restrict__ Wv,
                 const float* __restrict__ Wp)
{
    const int i4 = blockIdx.x * 256 + threadIdx.x;
    if (i4 < 1048576) {
        *(uint2*)(g_xh + (size_t)i4 * 4) = cvt4h(*(const float4*)(x + (size_t)i4 * 4));
    } else if (i4 < 1310720) {
        int j = (i4 - 1048576) * 4;
        int r = j >> 10, c = j & 1023;
        *(uint2*)(g_wch + (size_t)r * 2048 + c) = cvt4h(*(const float4*)(Wq + j));
    } else if (i4 < 1441792) {
        int j = (i4 - 1310720) * 4;
        int r = j >> 9, c = j & 511;
        *(uint2*)(g_wch + (size_t)r * 2048 + 1024 + c) = cvt4h(*(const float4*)(Wk + j));
    } else if (i4 < 1572864) {
        int j = (i4 - 1441792) * 4;
        int r = j >> 9, c = j & 511;
        *(uint2*)(g_wch + (size_t)r * 2048 + 1536 + c) = cvt4h(*(const float4*)(Wv + j));
    } else {
        int j = (i4 - 1572864) * 4;
        *(uint2*)(g_wph + j) = cvt4h(*(const float4*)(Wp + j));
    }
}

// ---------------- GEMM: C = A @ B, fp16 single, fp32 out (R11 shape) ---------
#define GSTAGE 18944
// stage: A@0 (128x40x2=10240), B@10240 (32x136x2=8704)

__global__ __launch_bounds__(256)
void gemm_f16(const __half* __restrict__ Ag, const __half* __restrict__ Bg,
              float* __restrict__ C, int M, int N, int K)
{
    extern __shared__ char sm[];
    const int tid = threadIdx.x;
    const int lane = tid & 31, wid = tid >> 5;
    const int warp_m = wid & 1, warp_n = wid >> 1;
    const int gid = lane >> 2, tig = lane & 3;
    const int lane15 = lane & 15, lhi8 = (lane >> 4) * 8;
    const int m0 = blockIdx.y * 128, n0 = blockIdx.x * 128;
    const uint32_t sb = (uint32_t)__cvta_generic_to_shared(sm);

    const int cc0 = tid * 2;
    const int ar = cc0 >> 2, ac = cc0 & 3;
    const int br = cc0 >> 4, bc = cc0 & 15;

    float acc[4][4][4];
#pragma unroll
    for (int i = 0; i < 4; i++)
#pragma unroll
        for (int j = 0; j < 4; j++)
#pragma unroll
            for (int r = 0; r < 4; r++) acc[i][j][r] = 0.f;

#define GEMM_LOAD(stg, k0) do { \
    uint32_t s_ = sb + (stg) * GSTAGE; \
    const __half* p_; \
    p_ = Ag + (size_t)(m0 + ar) * K + (k0) + ac * 8; \
    CP16(s_ + ar*80 + ac*16, p_); CP16(s_ + ar*80 + ac*16 + 16, p_ + 8); \
    p_ = Bg + (size_t)((k0) + br) * N + n0 + bc * 8; \
    CP16(s_ + 10240 + br*272 + bc*16, p_); CP16(s_ + 10240 + br*272 + bc*16 + 16, p_ + 8); \
    CP_COMMIT; \
} while (0)

    const int ktiles = K >> 5;
    GEMM_LOAD(0, 0);
    GEMM_LOAD(1, 32);

    int stg = 0;
    for (int t = 0; t < ktiles; t++) {
        if (t + 1 < ktiles) CP_WAIT(1); else CP_WAIT(0);
        __syncthreads();
        if (t + 2 < ktiles) {
            int ns = stg + 2; if (ns >= 3) ns -= 3;
            GEMM_LOAD(ns, (t + 2) * 32);
        }

        const uint32_t sA = sb + stg * GSTAGE;
        const uint32_t sB = sA + 10240;

#pragma unroll
        for (int ks = 0; ks < 2; ks++) {
            const uint32_t a_off = (uint32_t)((warp_m * 64 + lane15) * 80 + (ks * 16 + lhi8) * 2);
            const uint32_t b_off = (uint32_t)((ks * 16 + lane15) * 272 + (warp_n * 32 + lhi8) * 2);

            uint32_t a[4][4];
            uint32_t bh[2][4];
#pragma unroll
            for (int mf = 0; mf < 4; mf++)
                LDSM4(a[mf][0],a[mf][1],a[mf][2],a[mf][3], sA + a_off + (uint32_t)(mf * 16 * 80));
#pragma unroll
            for (int p = 0; p < 2; p++)
                LDSM4T(bh[p][0],bh[p][1],bh[p][2],bh[p][3], sB + b_off + (uint32_t)(p * 32));
#pragma unroll
            for (int mf = 0; mf < 4; mf++)
#pragma unroll
                for (int nf = 0; nf < 4; nf++) {
                    const int p = nf >> 1, q = (nf & 1) * 2;
                    MMA16816H(acc[mf][nf], a[mf], bh[p][q], bh[p][q+1]);
                }
        }
        stg++; if (stg == 3) stg = 0;
    }

#pragma unroll
    for (int mf = 0; mf < 4; mf++) {
#pragma unroll
        for (int nf = 0; nf < 4; nf++) {
            const int row = m0 + warp_m * 64 + mf * 16 + gid;
            const int col = n0 + warp_n * 32 + nf * 8 + tig * 2;
            *(float2*)&C[(size_t)row * N + col] = make_float2(acc[mf][nf][0], acc[mf][nf][1]);
            *(float2*)&C[(size_t)(row + 8) * N + col] = make_float2(acc[mf][nf][2], acc[mf][nf][3]);
        }
    }
}

// ---------------- postprocess: gate+ve, RoPE, rmsnorm, fp16 out --------------
__global__ __launch_bounds__(256)
void postproc(const float* __restrict__ x, const float* __restrict__ ve,
              const float* __restrict__ cosb, const float* __restrict__ sinb,
              const float* __restrict__ Wgate)
{
    const int bt = blockIdx.x;
    const int b = bt >> 11, t = bt & (TT - 1);
    const int tid = threadIdx.x;
    const float* qkv = g_qkvbuf + (size_t)bt * 2048;

    __shared__ float gate[NKV];
    if (tid < NKV) {
        float acc = 0.f;
        const float* xr = x + (size_t)bt * CC;
#pragma unroll
        for (int c = 0; c < 32; c++) acc += xr[c] * Wgate[c * NKV + tid];
        gate[tid] = 2.f / (1.f + expf(-acc));
    }
    __syncthreads();

    for (int i = tid; i < NKV * HD; i += 256) {
        int hh = i >> 6, d = i & 63;
        float vv = qkv[1536 + i] + gate[hh] * ve[(size_t)bt * 512 + i];
        g_vattn[(((size_t)b * NKV + hh) * TT + t) * HD + d] = __float2half(vv);
    }

    const int w = tid >> 5, lane = tid & 31;
    const float cs = cosb[t * 32 + lane];
    const float sn = sinb[t * 32 + lane];

#pragma unroll
    for (int qi = 0; qi < 2; qi++) {
        int h = 2 * w + qi;
        const float* qr = qkv + h * HD;
        float x1 = qr[lane], x2 = qr[lane + 32];
        float r1 = x1 * cs + x2 * sn;
        float r2 = -x1 * sn + x2 * cs;
        float ss = r1 * r1 + r2 * r2;
#pragma unroll
        for (int o = 16; o; o >>= 1) ss += __shfl_xor_sync(0xffffffffu, ss, o);
        float sc = rsqrtf(ss * (1.f / 64.f) + RMS_EPS) * QSCALE;
        size_t idx = (((size_t)b * NH + h) * TT + t) * HD;
        g_qattn[idx + lane]      = __float2half(r1 * sc);
        g_qattn[idx + lane + 32] = __float2half(r2 * sc);
    }
    {
        const float* kr = qkv + 1024 + w * HD;
        float x1 = kr[lane], x2 = kr[lane + 32];
        float r1 = x1 * cs + x2 * sn;
        float r2 = -x1 * sn + x2 * cs;
        float ss = r1 * r1 + r2 * r2;
#pragma unroll
        for (int o = 16; o; o >>= 1) ss += __shfl_xor_sync(0xffffffffu, ss, o);
        float sc = rsqrtf(ss * (1.f / 64.f) + RMS_EPS);
        size_t idx = (((size_t)b * NKV + w) * TT + t) * HD;
        g_kattn[idx + lane]      = __float2half(r1 * sc);
        g_kattn[idx + lane + 32] = __float2half(r2 * sc);
    }
}

// ---------------- flash attention: fixed-max softmax, l-via-MMA --------------
// BM=64, BN=64, 4 warps. smem: Q@0 (9216), 2 stages {K,V} at 9216+stg*18432,
// ones block @46080.  Total 46592.
// Scores bounded (rmsnorm): |s| <= 11.54 in exp2 domain -> fixed shift M=8.
// S accumulators init to -M; p = exp2(s-M); no running max, no corrections.
__global__ __launch_bounds__(128)
void attn_mma(const int* __restrict__ wptr)
{
    extern __shared__ char sm[];
    const uint32_t sb = (uint32_t)__cvta_generic_to_shared(sm);
    const uint32_t sQ = sb;
    const uint32_t sOnes = sb + 46080;

    const int qt0 = (int)(gridDim.x - 1 - blockIdx.x) * 64;   // heavy blocks first
    const int bh = blockIdx.y;
    const int b = bh >> 4, h = bh & 15;
    const int window = *wptr;
    const bool is_local = (h >= 8);
    const int kvh = is_local ? 4 + ((h - 8) >> 1) : (h >> 1);

    const __half* qb = g_qattn + ((size_t)(b * NH + h) * TT) * HD;
    const __half* kb = g_kattn + ((size_t)(b * NKV + kvh) * TT) * HD;
    const __half* vb = g_vattn + ((size_t)(b * NKV + kvh) * TT) * HD;

    const int tid = threadIdx.x;
    const int lane = tid & 31, wid = tid >> 5;
    const int gid = lane >> 2, tig = lane & 3;
    const int lane15 = lane & 15, lhi8 = (lane >> 4) * 8;
    const int krow = (lane & 7) | ((lane & 16) >> 1);
    const int kc8 = lane & 8;

#define ATT_LOAD(stg, ktv) do { \
    uint32_t base_ = sb + 9216 + (stg) * 18432; \
    for (int c = tid; c < 512; c += 128) { \
        int row_ = c >> 3, c8_ = c & 7; \
        size_t g_ = (size_t)((ktv) + row_) * HD + c8_ * 8; \
        uint32_t d_ = base_ + row_ * 144 + c8_ * 16; \
        CP16(d_, kb + g_); CP16(d_ + 9216, vb + g_); \
    } CP_COMMIT; \
} while (0)

    int t0 = 0;
    if (is_local) { int s = qt0 - window; t0 = (s > 0 ? s : 0) & ~63; }
    const int nt = (qt0 - t0) / 64 + 1;

    if (tid < 128) {
        int k = tid >> 3, c2 = (tid & 7) * 2;
        uint32_t v = (c2 == 0) ? 0x00003C00u : 0u;
        asm volatile("st.shared.b32 [%0], %1;" :: "r"(sOnes + k * 32 + c2 * 2), "r"(v));
    }

    for (int c = tid; c < 512; c += 128) {
        int row = c >> 3, c8 = c & 7;
        CP16(sQ + row * 144 + c8 * 16, qb + (size_t)(qt0 + row) * HD + c8 * 8);
    }
    CP_COMMIT;
    ATT_LOAD(0, t0);
    CP_WAIT(1);
    __syncthreads();

    uint32_t qf[4][4];
    {
        const uint32_t qa = (uint32_t)((wid * 16 + lane15) * 144 + lhi8 * 2);
#pragma unroll
        for (int ks = 0; ks < 4; ks++)
            LDSM4(qf[ks][0],qf[ks][1],qf[ks][2],qf[ks][3], sQ + qa + ks * 32);
    }
    uint32_t ob0, ob1, ob2, ob3;
    LDSM4T(ob0, ob1, ob2, ob3, sOnes + (uint32_t)(lane15 * 32 + lhi8 * 2));
    (void)ob2; (void)ob3;

    float o[8][4];
#pragma unroll
    for (int nf = 0; nf < 8; nf++)
#pragma unroll
        for (int r = 0; r < 4; r++) o[nf][r] = 0.f;
    float ol[4] = {0.f, 0.f, 0.f, 0.f};     // col 0 = row sum l (M-shifted domain)

    const int i0 = qt0 + wid * 16 + gid, i1 = i0 + 8;

    for (int it = 0; it < nt; it++) {
        const int kt = t0 + it * 64;
        const int stg = it & 1;
        if (it + 1 < nt) { ATT_LOAD(stg ^ 1, kt + 64); CP_WAIT(1); }
        else             { CP_WAIT(0); }
        __syncthreads();

        const uint32_t sK = sb + 9216 + stg * 18432;
        const uint32_t sV = sK + 9216;

        // ---- S = Q K^T - M  (accumulators seeded with -M)
        float s[8][4];
#pragma unroll
        for (int nf = 0; nf < 8; nf++)
#pragma unroll
            for (int r = 0; r < 4; r++) s[nf][r] = -SOFTMAX_M;
#pragma unroll
        for (int ks = 0; ks < 4; ks++) {
#pragma unroll
            for (int g = 0; g < 4; g++) {
                const uint32_t ka = (uint32_t)((g * 16 + krow) * 144 + (ks * 16 + kc8) * 2);
                uint32_t b0,b1,b2,b3;
                LDSM4(b0,b1,b2,b3, sK + ka);
                MMA16816H(s[2*g],   qf[ks], b0, b1);
                MMA16816H(s[2*g+1], qf[ks], b2, b3);
            }
        }

        // ---- mask only boundary tiles
        const bool need_mask = (kt + 64 > qt0) ||
                               (is_local && kt + window < qt0 + 64);
        if (need_mask) {
#pragma unroll
            for (int nf = 0; nf < 8; nf++) {
                int j0 = kt + nf * 8 + tig * 2, j1 = j0 + 1;
                bool k00 = (j0 <= i0) && (!is_local || j0 >= i0 - window);
                bool k01 = (j1 <= i0) && (!is_local || j1 >= i0 - window);
                bool k10 = (j0 <= i1) && (!is_local || j0 >= i1 - window);
                bool k11 = (j1 <= i1) && (!is_local || j1 >= i1 - window);
                if (!k00) s[nf][0] = -1e30f;
                if (!k01) s[nf][1] = -1e30f;
                if (!k10) s[nf][2] = -1e30f;
                if (!k11) s[nf][3] = -1e30f;
            }
        }

        // ---- p = exp2(s - M) in packed fp16 (masked -> -Inf -> 0)
        uint32_t pp0[8], pp1[8];
#pragma unroll
        for (int nf = 0; nf < 8; nf++) {
            uint32_t d0, d1;
            CVTF16X2(d0, s[nf][0], s[nf][1]);
            CVTF16X2(d1, s[nf][2], s[nf][3]);
            HEX2(pp0[nf], d0);
            HEX2(pp1[nf], d1);
        }

        // ---- O += P V   and   l += P · ones   (no corrections needed)
#pragma unroll
        for (int ks = 0; ks < 4; ks++) {
            uint32_t pf[4] = { pp0[2*ks], pp1[2*ks], pp0[2*ks+1], pp1[2*ks+1] };
#pragma unroll
            for (int g = 0; g < 4; g++) {
                const uint32_t va = (uint32_t)((ks * 16 + lane15) * 144 + (g * 16 + lhi8) * 2);
                uint32_t v0,v1,v2,v3;
                LDSM4T(v0,v1,v2,v3, sV + va);
                MMA16816H(o[2*g],   pf, v0, v1);
                MMA16816H(o[2*g+1], pf, v2, v3);
            }
            MMA16816H(ol, pf, ob0, ob1);
        }
        __syncthreads();
    }

    // ---- epilogue: y = O / l (M-shift cancels exactly)
    const float l0 = __shfl_sync(0xffffffffu, ol[0], lane & ~3);
    const float l1 = __shfl_sync(0xffffffffu, ol[2], lane & ~3);
    const float inv0 = 1.f / l0, inv1 = 1.f / l1;
    const int row0 = qt0 + wid * 16 + gid;
#pragma unroll
    for (int nf = 0; nf < 8; nf++) {
        const int col = h * 64 + nf * 8 + tig * 2;
        uint32_t u0, u1;
        CVTF16X2(u0, o[nf][0] * inv0, o[nf][1] * inv0);
        CVTF16X2(u1, o[nf][2] * inv1, o[nf][3] * inv1);
        *(uint32_t*)(g_yattn + (size_t)(b * TT + row0) * CC + col) = u0;
        *(uint32_t*)(g_yattn + (size_t)(b * TT + row0 + 8) * CC + col) = u1;
    }
}

// ---------------- launch ------------------------------------------------------
extern "C" void kernel_launch(void* const* d_in, const int* in_sizes, int n_in,
                              void* d_out, int out_size)
{
    const float* x     = (const float*)d_in[0];
    const float* ve    = (const float*)d_in[1];
    const float* cosb  = (const float*)d_in[2];
    const float* sinb  = (const float*)d_in[3];
    const float* Wq    = (const float*)d_in[4];
    const float* Wk    = (const float*)d_in[5];
    const float* Wv    = (const float*)d_in[6];
    const float* Wproj = (const float*)d_in[7];
    const float* Wgate = (const float*)d_in[8];
    const int*   wptr  = (const int*)d_in[9];

    float* qkvbuf;
    cudaGetSymbolAddress((void**)&qkvbuf, g_qkvbuf);
    __half *xh, *wch, *wph, *yh;
    cudaGetSymbolAddress((void**)&xh, g_xh);
    cudaGetSymbolAddress((void**)&wch, g_wch);
    cudaGetSymbolAddress((void**)&wph, g_wph);
    cudaGetSymbolAddress((void**)&yh, g_yattn);

    cudaFuncSetAttribute(gemm_f16, cudaFuncAttributeMaxDynamicSharedMemorySize, 3 * GSTAGE);
    cudaFuncSetAttribute(attn_mma, cudaFuncAttributeMaxDynamicSharedMemorySize, 46592);

    // fused conversion (x, Wq, Wk, Wv, Wproj -> fp16)
    convert_all<<<7168, 256>>>(x, Wq, Wk, Wv, Wproj);

    // fused QKV projection (fp16) -> fp32 qkv
    gemm_f16<<<dim3(16, 32), 256, 3 * GSTAGE>>>(xh, wch, qkvbuf, BT, 2048, CC);

    // gate + ve, rope, rmsnorm -> fp16 q/k/v (q pre-scaled, exp2 domain)
    postproc<<<BT, 256>>>(x, ve, cosb, sinb, Wgate);

    // attention (fixed-max softmax) -> fp16 y
    attn_mma<<<dim3(TT / 64, BB * NH), 128, 46592>>>(wptr);

    // output projection (fp16) -> d_out
    gemm_f16<<<dim3(8, 32), 256, 3 * GSTAGE>>>(yh, wph, (float*)d_out, BT, 1024, CC);
}